// round 7
// baseline (speedup 1.0000x reference)
#include <cuda_runtime.h>
#include <cuda_bf16.h>
#include <cstdint>

#define BATCH 8
#define CIN 256
#define COUT 128
#define HIN 60
#define WIN 80
#define HUP 122
#define HOUT 120
#define WOUT 160
#define NPIX (HOUT*WOUT)   // 19200

// ---------------------------------------------------------------------------
// Device-global scratch
// ---------------------------------------------------------------------------
__device__ __align__(16) float         g_dw[(size_t)BATCH * CIN * NPIX]; // [b][c][p]
__device__ __align__(16) __nv_bfloat16 g_Ah[COUT * CIN];                 // pw hi [o][c]
__device__ __align__(16) __nv_bfloat16 g_Al[COUT * CIN];                 // pw lo [o][c]

// ---------------------------------------------------------------------------
// Kernel: split pointwise weights [o][c] fp32 -> bf16 hi/lo
// ---------------------------------------------------------------------------
__global__ void pwsplit_kernel(const float* __restrict__ pw) {
    int i = blockIdx.x * 256 + threadIdx.x;          // 0..32767
    float v = pw[i];
    __nv_bfloat16 h = __float2bfloat16(v);
    __nv_bfloat16 l = __float2bfloat16(v - __bfloat162float(h));
    g_Ah[i] = h;
    g_Al[i] = l;
}

// ---------------------------------------------------------------------------
// Kernel: bilinear upsample (align_corners) + 3x3 depthwise VALID
// Now with precomputed per-column x0/fx tables.
// ---------------------------------------------------------------------------
__global__ __launch_bounds__(256) void dw_kernel(const float* __restrict__ x,
                                                 const float* __restrict__ wdw) {
    __shared__ float vs[HUP * WIN];                  // 39040 B
    __shared__ float fxs[162];
    __shared__ int   x0s[162];

    int bc = blockIdx.x;
    int c  = bc & (CIN - 1);
    const float* xp = x + (size_t)bc * (HIN * WIN);
    float* op = g_dw + (size_t)bc * NPIX;
    int tid = threadIdx.x;

    const float SY = (float)(59.0 / 121.0);
    const float SX = (float)(79.0 / 161.0);

    // per-column horizontal interp table
    if (tid < 162) {
        float wx  = tid * SX;
        float x0f = floorf(wx);
        int   x0  = (int)x0f;
        fxs[tid] = wx - x0f;
        x0s[tid] = x0;                               // x0 <= 78, x0+1 <= 79 in-range
    }

    // vertical interpolation into smem
    for (int i = tid; i < HUP * WIN; i += 256) {
        int rr = i / WIN;
        int xc = i - rr * WIN;
        float hy  = rr * SY;
        float y0f = floorf(hy);
        int   y0  = (int)y0f;
        float fy  = hy - y0f;
        int   y1  = y0 + 1; if (y1 > HIN - 1) y1 = HIN - 1;
        float a  = xp[y0 * WIN + xc];
        float b2 = xp[y1 * WIN + xc];
        vs[i] = a + fy * (b2 - a);
    }

    float kd[9];
#pragma unroll
    for (int t = 0; t < 9; t++) kd[t] = __ldg(wdw + c * 9 + t);

    __syncthreads();

    for (int s = tid; s < 2400; s += 256) {
        int h  = s / 20;
        int w0 = (s - h * 20) * 8;

        float u[3][10];
#pragma unroll
        for (int j = 0; j < 10; j++) {
            int   cc = w0 + j;
            int   x0 = x0s[cc];
            float fx = fxs[cc];
#pragma unroll
            for (int i2 = 0; i2 < 3; i2++) {
                const float* vr = vs + (h + i2) * WIN;
                float a  = vr[x0];
                float b2 = vr[x0 + 1];
                u[i2][j] = a + fx * (b2 - a);
            }
        }

        float res[8];
#pragma unroll
        for (int ww = 0; ww < 8; ww++) {
            float acc = 0.0f;
#pragma unroll
            for (int i2 = 0; i2 < 3; i2++)
#pragma unroll
                for (int j = 0; j < 3; j++)
                    acc = fmaf(kd[i2 * 3 + j], u[i2][ww + j], acc);
            res[ww] = acc;
        }

        float4* dst = (float4*)(op + h * WOUT + w0);
        dst[0] = make_float4(res[0], res[1], res[2], res[3]);
        dst[1] = make_float4(res[4], res[5], res[6], res[7]);
    }
}

// ---------------------------------------------------------------------------
// GEMM via mma.sync (HMMA) split-bf16 3-pass, ldmatrix fragment loads.
// Block 128(o) x 128(p), 8 warps, warp tile 64x32, K chunks of 32.
// ---------------------------------------------------------------------------
#define APAD 40    // A smem row stride (bf16 elems): 80 B -> LDSM conflict-free
#define BPAD 136   // B smem row stride (elems): 272 B -> LDSM conflict-free

__device__ __forceinline__ uint32_t smem_u32(const void* p) {
    uint32_t a;
    asm("{ .reg .u64 t; cvta.to.shared.u64 t, %1; cvt.u32.u64 %0, t; }" : "=r"(a) : "l"(p));
    return a;
}
__device__ __forceinline__ void mma_bf16(float* d, const uint32_t* a, const uint32_t* b) {
    asm volatile(
        "mma.sync.aligned.m16n8k16.row.col.f32.bf16.bf16.f32 "
        "{%0,%1,%2,%3}, {%4,%5,%6,%7}, {%8,%9}, {%0,%1,%2,%3};"
        : "+f"(d[0]), "+f"(d[1]), "+f"(d[2]), "+f"(d[3])
        : "r"(a[0]), "r"(a[1]), "r"(a[2]), "r"(a[3]), "r"(b[0]), "r"(b[1]));
}
__device__ __forceinline__ void ldsm_x4(uint32_t* r, uint32_t addr) {
    asm volatile("ldmatrix.sync.aligned.m8n8.x4.shared.b16 {%0,%1,%2,%3}, [%4];"
        : "=r"(r[0]), "=r"(r[1]), "=r"(r[2]), "=r"(r[3]) : "r"(addr));
}
__device__ __forceinline__ void ldsm_x4_t(uint32_t* r, uint32_t addr) {
    asm volatile("ldmatrix.sync.aligned.m8n8.x4.trans.shared.b16 {%0,%1,%2,%3}, [%4];"
        : "=r"(r[0]), "=r"(r[1]), "=r"(r[2]), "=r"(r[3]) : "r"(addr));
}

__global__ __launch_bounds__(256, 2) void gemm_kernel(float* __restrict__ out) {
    __shared__ __align__(16) __nv_bfloat16 Ash[128 * APAD];   // 10240 B
    __shared__ __align__(16) __nv_bfloat16 Als[128 * APAD];   // 10240 B
    __shared__ __align__(16) unsigned short Bhs[32 * BPAD];   //  8704 B
    __shared__ __align__(16) unsigned short Bls[32 * BPAD];   //  8704 B

    int tid  = threadIdx.x;
    int lane = tid & 31;
    int wid  = tid >> 5;

    int b  = blockIdx.x / (NPIX / 128);              // 150 p-tiles per batch
    int p0 = (blockIdx.x - b * (NPIX / 128)) * 128;

    const float* dwp = g_dw + (size_t)b * CIN * NPIX + p0;

    int mw = (wid >> 2) * 64;                        // warp M offset
    int nw = (wid & 3) * 32;                         // warp N offset
    int g  = lane >> 2;
    int q  = lane & 3;

    // ldmatrix lane-address components
    int lrow = lane & 15;                            // row within 16-row group
    int lhi  = (lane >> 4) * 8;                      // +8 col/row-group for upper half
    uint32_t aA_base = smem_u32(Ash) + ((mw + lrow) * APAD + lhi) * 2;
    uint32_t aL_base = smem_u32(Als) + ((mw + lrow) * APAD + lhi) * 2;
    uint32_t bH_base = smem_u32(Bhs) + (lrow * BPAD + nw + lhi) * 2;
    uint32_t bL_base = smem_u32(Bls) + (lrow * BPAD + nw + lhi) * 2;

    float acc[4][4][4];
#pragma unroll
    for (int i = 0; i < 4; i++)
#pragma unroll
        for (int j = 0; j < 4; j++)
#pragma unroll
            for (int k = 0; k < 4; k++) acc[i][j][k] = 0.0f;

    for (int ck = 0; ck < CIN / 32; ++ck) {
        __syncthreads();                             // protect prev-iter reads

        // --- load A chunk [128 o][32 k] bf16 hi+lo ---
#pragma unroll
        for (int i = 0; i < 2; i++) {
            int idx = tid + i * 256;
            int o = idx >> 2, qq = idx & 3;
            size_t goff = (size_t)o * 512 + (size_t)ck * 64 + qq * 16;
            uint4 vh = *(const uint4*)((const char*)g_Ah + goff);
            uint4 vl = *(const uint4*)((const char*)g_Al + goff);
            *(uint4*)((char*)Ash + o * (APAD * 2) + qq * 16) = vh;
            *(uint4*)((char*)Als + o * (APAD * 2) + qq * 16) = vl;
        }

        // --- load B chunk [32 c][128 p] fp32 -> bf16 hi/lo ---
#pragma unroll
        for (int i = 0; i < 4; i++) {
            int idx = tid + i * 256;
            int c  = idx >> 5;
            int p4 = (idx & 31) * 4;
            float4 v = *(const float4*)(dwp + (size_t)(ck * 32 + c) * NPIX + p4);
            float vv[4] = {v.x, v.y, v.z, v.w};
            uint32_t h[4], l[4];
#pragma unroll
            for (int j = 0; j < 4; j++) {
                __nv_bfloat16 hh = __float2bfloat16(vv[j]);
                __nv_bfloat16 ll = __float2bfloat16(vv[j] - __bfloat162float(hh));
                h[j] = (uint32_t)__bfloat16_as_ushort(hh);
                l[j] = (uint32_t)__bfloat16_as_ushort(ll);
            }
            *(uint2*)&Bhs[c * BPAD + p4] =
                make_uint2(h[0] | (h[1] << 16), h[2] | (h[3] << 16));
            *(uint2*)&Bls[c * BPAD + p4] =
                make_uint2(l[0] | (l[1] << 16), l[2] | (l[3] << 16));
        }
        __syncthreads();

        // --- compute: 2 k16 steps ---
#pragma unroll
        for (int kk = 0; kk < 32; kk += 16) {
            // B fragments: x4.trans covers n16 x k16 -> 2 n-tiles per ldmatrix
            uint32_t bh[4][2], bl[4][2];
#pragma unroll
            for (int t = 0; t < 2; t++) {
                uint32_t r[4];
                ldsm_x4_t(r, bH_base + (kk * BPAD + t * 16) * 2);
                bh[t * 2][0] = r[0]; bh[t * 2][1] = r[1];
                bh[t * 2 + 1][0] = r[2]; bh[t * 2 + 1][1] = r[3];
                ldsm_x4_t(r, bL_base + (kk * BPAD + t * 16) * 2);
                bl[t * 2][0] = r[0]; bl[t * 2][1] = r[1];
                bl[t * 2 + 1][0] = r[2]; bl[t * 2 + 1][1] = r[3];
            }

#pragma unroll
            for (int mt = 0; mt < 4; mt++) {
                uint32_t ah[4], al[4];
                ldsm_x4(ah, aA_base + (mt * 16 * APAD + kk) * 2);
                ldsm_x4(al, aL_base + (mt * 16 * APAD + kk) * 2);
#pragma unroll
                for (int nt = 0; nt < 4; nt++)
                    mma_bf16(acc[mt][nt], ah, bh[nt]);
#pragma unroll
                for (int nt = 0; nt < 4; nt++)
                    mma_bf16(acc[mt][nt], al, bh[nt]);
#pragma unroll
                for (int nt = 0; nt < 4; nt++)
                    mma_bf16(acc[mt][nt], ah, bl[nt]);
            }
        }
    }

    // --- epilogue ---
    float* base = out + (size_t)b * COUT * NPIX + p0;
#pragma unroll
    for (int mt = 0; mt < 4; mt++) {
#pragma unroll
        for (int nt = 0; nt < 4; nt++) {
            int m = mw + mt * 16 + g;
            int n = nw + nt * 8 + q * 2;
            *(float2*)&base[(size_t)m * NPIX + n] =
                make_float2(acc[mt][nt][0], acc[mt][nt][1]);
            *(float2*)&base[(size_t)(m + 8) * NPIX + n] =
                make_float2(acc[mt][nt][2], acc[mt][nt][3]);
        }
    }
}

// ---------------------------------------------------------------------------
// Launch
// ---------------------------------------------------------------------------
extern "C" void kernel_launch(void* const* d_in, const int* in_sizes, int n_in,
                              void* d_out, int out_size) {
    const float* x   = (const float*)d_in[0];   // [8,256,60,80]
    const float* wdw = (const float*)d_in[1];   // [256,1,3,3]
    const float* wpw = (const float*)d_in[2];   // [128,256]
    float* out = (float*)d_out;                 // [8,128,120,160]

    pwsplit_kernel<<<128, 256>>>(wpw);
    dw_kernel<<<BATCH * CIN, 256>>>(x, wdw);
    gemm_kernel<<<BATCH * (NPIX / 128), 256>>>(out);
}